// round 8
// baseline (speedup 1.0000x reference)
#include <cuda_runtime.h>
#include <cuda_fp16.h>
#include <mma.h>
#include <cstdint>

using namespace nvcuda;

// Problem constants: N=50000, E=640000, D=H=128, OUT=32
#define MAXN 50000
#define MAXE 640000

// Scratch (device globals — no allocation allowed)
__device__ float g_W3[128 * 512];     // [Wp | Wp@WmA | Wp@WmB | Wp@WuA]
__device__ float g_b3[512];           // [bp | bp@WmA | bp@WmB+bm | bp@WuA]
__device__ float g_Y[MAXN * 256];     // per node: h0 (0..127) | c (128..255)  fp32
__device__ half2 g_a[MAXN * 64];      // a = h0@WmA          fp16 (L2-resident, random-read)
__device__ float g_b[MAXN * 128];     // b = h0@WmB + bm     fp32 (sequential)
__device__ float g_pool[MAXN * 128];  // pooled mean
__device__ float g_gsum[128];         // graph-level sum of normalized hn
__device__ int   g_deg[MAXN];         // per-dst degree
__device__ int   g_off[MAXN];         // CSR offsets
__device__ int   g_cur[MAXN];         // scatter cursors
__device__ int   g_elist[MAXE];       // src ids grouped by dst

// ---------------------------------------------------------------------------
__global__ void k_zero(int n) {
    int i = blockIdx.x * blockDim.x + threadIdx.x;
    if (i < n) g_deg[i] = 0;
}

// ---------------------------------------------------------------------------
// Build combined weights/biases: W3 = [Wp | Wp@WmA | Wp@WmB | Wp@WuA]
// ---------------------------------------------------------------------------
__global__ void k_prep(const float* __restrict__ Wp, const float* __restrict__ bp,
                       const float* __restrict__ Wm, const float* __restrict__ bm,
                       const float* __restrict__ Wu) {
    int idx = blockIdx.x * blockDim.x + threadIdx.x;
    if (idx < 128 * 512) {
        int i = idx >> 9;
        int j = idx & 511;
        int blk = j >> 7, jj = j & 127;
        float v;
        if (blk == 0) {
            v = Wp[i * 128 + jj];
        } else {
            const float* M = (blk == 1) ? Wm : (blk == 2 ? Wm + 16384 : Wu);
            float s = 0.f;
            for (int k = 0; k < 128; k++) s += Wp[i * 128 + k] * M[k * 128 + jj];
            v = s;
        }
        g_W3[idx] = v;
    }
    if (idx < 512) {
        int blk = idx >> 7, jj = idx & 127;
        float v;
        if (blk == 0) {
            v = bp[jj];
        } else {
            const float* M = (blk == 1) ? Wm : (blk == 2 ? Wm + 16384 : Wu);
            float s = (blk == 2) ? bm[jj] : 0.f;
            for (int k = 0; k < 128; k++) s += bp[k] * M[k * 128 + jj];
            v = s;
        }
        g_b3[idx] = v;
    }
}

// ---------------------------------------------------------------------------
// fp16 wmma GEMM, CTA = 128x128 tile, K=128 in smem.
// mode 0 (grid.x=4): Y = x @ W3 + b3; block 0->g_Y h0 (fp32), 1->g_a (fp16),
//                    2->g_b (fp32), 3->g_Y c (fp32)
// mode 1 (grid.x=1): fused upd-GEMM + relu + LayerNorm + graph-pool partials
// ---------------------------------------------------------------------------
#define LDH 136
#define LDC 132
#define SM_A_BYTES (128 * LDH * 2)          // 34816
#define SACC_OFF   (2 * SM_A_BYTES)         // 69632 (after As+Bs; Cs ends at 67584)
#define GSM_SZ     (SACC_OFF + 4096)        // 73728

__global__ void __launch_bounds__(256, 2) k_gemm_h(const float* __restrict__ Xext,
                                                   const float* __restrict__ Wext,
                                                   const float* __restrict__ biasExt,
                                                   const float* __restrict__ gamma,
                                                   const float* __restrict__ beta,
                                                   int n, int mode) {
    extern __shared__ __align__(16) char smw[];
    half*  As = (half*)smw;
    half*  Bs = (half*)(smw + SM_A_BYTES);
    float* Cs = (float*)smw;                    // overlaps A+B (after sync)
    float* sacc = (float*)(smw + SACC_OFF);     // [8][128] LN partials

    const float* X    = mode ? g_pool : Xext;
    const float* W    = mode ? Wext   : g_W3;
    const float* bias = mode ? biasExt : g_b3;
    const int wp4     = mode ? 32 : 128;   // W row pitch (float4)
    const int rowBase = blockIdx.y * 128;
    const int cb4     = blockIdx.x * 32;   // W column base (float4)

    const int tid = threadIdx.x;
    const int wid = tid >> 5;
    const int lane = tid & 31;

    // ---- Fill A and B tiles (fp32 -> fp16) ----
    const float4* X4 = (const float4*)X;
    const float4* W4 = (const float4*)W;
    #pragma unroll
    for (int it = 0; it < 16; it++) {
        int i = tid + it * 256;
        int m = i >> 5, c4 = i & 31;
        int row = rowBase + m;
        float4 v = make_float4(0.f, 0.f, 0.f, 0.f);
        if (row < n) v = X4[(size_t)row * 32 + c4];
        half2* da = (half2*)&As[m * LDH + c4 * 4];
        da[0] = __floats2half2_rn(v.x, v.y);
        da[1] = __floats2half2_rn(v.z, v.w);

        float4 w = W4[(size_t)m * wp4 + cb4 + c4];
        half2* db = (half2*)&Bs[m * LDH + c4 * 4];
        db[0] = __floats2half2_rn(w.x, w.y);
        db[1] = __floats2half2_rn(w.z, w.w);
    }
    __syncthreads();

    // ---- MMA main loop ----
    const int wrow = (wid & 3) * 32;
    const int wcol = (wid >> 2) * 64;

    wmma::fragment<wmma::accumulator, 16, 16, 16, float> acc[2][4];
    #pragma unroll
    for (int r = 0; r < 2; r++)
        #pragma unroll
        for (int c = 0; c < 4; c++) wmma::fill_fragment(acc[r][c], 0.0f);

    #pragma unroll
    for (int kk = 0; kk < 8; kk++) {
        wmma::fragment<wmma::matrix_a, 16, 16, 16, half, wmma::row_major> af[2];
        wmma::fragment<wmma::matrix_b, 16, 16, 16, half, wmma::row_major> bf[4];
        #pragma unroll
        for (int r = 0; r < 2; r++)
            wmma::load_matrix_sync(af[r], &As[(wrow + r * 16) * LDH + kk * 16], LDH);
        #pragma unroll
        for (int c = 0; c < 4; c++)
            wmma::load_matrix_sync(bf[c], &Bs[(kk * 16) * LDH + wcol + c * 16], LDH);
        #pragma unroll
        for (int r = 0; r < 2; r++)
            #pragma unroll
            for (int c = 0; c < 4; c++)
                wmma::mma_sync(acc[r][c], af[r], bf[c], acc[r][c]);
    }

    // ---- Stage C (fp32) into smem ----
    __syncthreads();
    #pragma unroll
    for (int r = 0; r < 2; r++)
        #pragma unroll
        for (int c = 0; c < 4; c++)
            wmma::store_matrix_sync(&Cs[(wrow + r * 16) * LDC + wcol + c * 16],
                                    acc[r][c], LDC, wmma::mem_row_major);
    __syncthreads();

    const float4* b4 = (const float4*)bias;

    if (mode == 0) {
        const int blk = blockIdx.x;
        #pragma unroll
        for (int it = 0; it < 16; it++) {
            int i = tid + it * 256;
            int m = i >> 5, c4 = i & 31;
            int row = rowBase + m;
            if (row >= n) continue;
            float4 v = *(float4*)&Cs[m * LDC + c4 * 4];
            float4 bv = b4[cb4 + c4];
            v.x += bv.x; v.y += bv.y; v.z += bv.z; v.w += bv.w;
            if (blk == 0) {
                ((float4*)g_Y)[(size_t)row * 64 + c4] = v;            // h0
            } else if (blk == 3) {
                ((float4*)g_Y)[(size_t)row * 64 + 32 + c4] = v;       // c
            } else if (blk == 2) {
                ((float4*)g_b)[(size_t)row * 32 + c4] = v;            // b fp32
            } else {
                half2 h0 = __floats2half2_rn(v.x, v.y);               // a fp16
                half2 h1 = __floats2half2_rn(v.z, v.w);
                g_a[(size_t)row * 64 + c4 * 2]     = h0;
                g_a[(size_t)row * 64 + c4 * 2 + 1] = h1;
            }
        }
    } else {
        // ---- Fused: upd + relu(h0+c+upd) + LayerNorm + graph-pool partials ----
        float4 ga = ((const float4*)gamma)[lane];
        float4 be = ((const float4*)beta)[lane];
        float ax = 0.f, ay = 0.f, az = 0.f, aw = 0.f;
        float4 bv = b4[lane];   // bu

        #pragma unroll
        for (int it = 0; it < 16; it++) {
            int m = (tid >> 5) + it * 8;      // one warp <-> one row
            int row = rowBase + m;
            if (row >= n) continue;
            float4 u = *(float4*)&Cs[m * LDC + lane * 4];
            float4 h0 = ((const float4*)g_Y)[(size_t)row * 64 + lane];
            float4 cv = ((const float4*)g_Y)[(size_t)row * 64 + 32 + lane];
            float vx = fmaxf(h0.x + cv.x + u.x + bv.x, 0.f);
            float vy = fmaxf(h0.y + cv.y + u.y + bv.y, 0.f);
            float vz = fmaxf(h0.z + cv.z + u.z + bv.z, 0.f);
            float vw = fmaxf(h0.w + cv.w + u.w + bv.w, 0.f);

            float s1 = vx + vy + vz + vw;
            float s2 = vx * vx + vy * vy + vz * vz + vw * vw;
            #pragma unroll
            for (int o = 16; o > 0; o >>= 1) {
                s1 += __shfl_xor_sync(0xFFFFFFFFu, s1, o);
                s2 += __shfl_xor_sync(0xFFFFFFFFu, s2, o);
            }
            float mu  = s1 * (1.f / 128.f);
            float var = s2 * (1.f / 128.f) - mu * mu;
            float is  = rsqrtf(var + 1e-6f);
            ax += (vx - mu) * is * ga.x + be.x;
            ay += (vy - mu) * is * ga.y + be.y;
            az += (vz - mu) * is * ga.z + be.z;
            aw += (vw - mu) * is * ga.w + be.w;
        }

        sacc[wid * 128 + lane * 4 + 0] = ax;
        sacc[wid * 128 + lane * 4 + 1] = ay;
        sacc[wid * 128 + lane * 4 + 2] = az;
        sacc[wid * 128 + lane * 4 + 3] = aw;
        __syncthreads();
        if (tid < 128) {
            float s = 0.f;
            #pragma unroll
            for (int ww = 0; ww < 8; ww++) s += sacc[ww * 128 + tid];
            atomicAdd(&g_gsum[tid], s);
        }
    }
}

// ---------------------------------------------------------------------------
// CSR build: histogram -> single-block scan -> scatter
// ---------------------------------------------------------------------------
__global__ void k_hist(const int* __restrict__ dst, int e) {
    int i = blockIdx.x * blockDim.x + threadIdx.x;
    if (i < e) atomicAdd(&g_deg[dst[i]], 1);
}

__global__ void __launch_bounds__(1024) k_scan(int n) {
    __shared__ int wsum[32];
    int tid = threadIdx.x;
    int lane = tid & 31, wd = tid >> 5;
    int chunk = (n + 1023) / 1024;
    int lo = tid * chunk; if (lo > n) lo = n;
    int hi = lo + chunk;  if (hi > n) hi = n;
    int s = 0;
    for (int i = lo; i < hi; i++) s += g_deg[i];
    int v = s;
    #pragma unroll
    for (int o = 1; o < 32; o <<= 1) {
        int t = __shfl_up_sync(0xFFFFFFFFu, v, o);
        if (lane >= o) v += t;
    }
    if (lane == 31) wsum[wd] = v;
    __syncthreads();
    if (wd == 0) {
        int w = wsum[lane];
        #pragma unroll
        for (int o = 1; o < 32; o <<= 1) {
            int t = __shfl_up_sync(0xFFFFFFFFu, w, o);
            if (lane >= o) w += t;
        }
        wsum[lane] = w;
    }
    __syncthreads();
    int base = v - s + (wd > 0 ? wsum[wd - 1] : 0);
    for (int i = lo; i < hi; i++) {
        g_off[i] = base;
        g_cur[i] = base;
        base += g_deg[i];
    }
    if (tid < 128) g_gsum[tid] = 0.f;
}

__global__ void k_scatter(const int* __restrict__ src, const int* __restrict__ dst, int e) {
    int i = blockIdx.x * blockDim.x + threadIdx.x;
    if (i < e) {
        int pos = atomicAdd(&g_cur[dst[i]], 1);
        g_elist[pos] = src[i];
    }
}

// ---------------------------------------------------------------------------
// Gather: warp per node d. pooled[d] = mean over edges of relu(a[src]+b[d]).
// a rows are fp16 (256B, L2-resident); b row fp32 sequential.
// ---------------------------------------------------------------------------
__global__ void __launch_bounds__(256) k_gather(int n) {
    int w = (blockIdx.x * blockDim.x + threadIdx.x) >> 5;
    if (w >= n) return;
    int lane = threadIdx.x & 31;
    int off = g_off[w], deg = g_deg[w];

    float4 vb = __ldg(((const float4*)g_b) + (size_t)w * 32 + lane);
    float ax = 0.f, ay = 0.f, az = 0.f, aw = 0.f;

    int s = (deg > 0) ? g_elist[off] : 0;
    for (int j = 0; j < deg; j++) {
        int s2 = (j + 1 < deg) ? g_elist[off + j + 1] : 0;
        half2 h0 = __ldg(g_a + (size_t)s * 64 + lane * 2);
        half2 h1 = __ldg(g_a + (size_t)s * 64 + lane * 2 + 1);
        float2 a01 = __half22float2(h0);
        float2 a23 = __half22float2(h1);
        ax += fmaxf(a01.x + vb.x, 0.f);
        ay += fmaxf(a01.y + vb.y, 0.f);
        az += fmaxf(a23.x + vb.z, 0.f);
        aw += fmaxf(a23.y + vb.w, 0.f);
        s = s2;
    }
    float rc = 1.0f / (float)max(deg, 1);
    float4 o = make_float4(ax * rc, ay * rc, az * rc, aw * rc);
    ((float4*)g_pool)[(size_t)w * 32 + lane] = o;
}

// ---------------------------------------------------------------------------
__global__ void k_final(const float* __restrict__ Wd, const float* __restrict__ bd,
                        float* __restrict__ out, int n) {
    int o = threadIdx.x;
    if (o >= 32) return;
    float s = 0.f;
    #pragma unroll
    for (int c = 0; c < 128; c++) s += g_gsum[c] * Wd[c * 32 + o];
    out[o] = s / (float)n + bd[o];
}

// ---------------------------------------------------------------------------
extern "C" void kernel_launch(void* const* d_in, const int* in_sizes, int n_in,
                              void* d_out, int out_size) {
    const float* x     = (const float*)d_in[0];
    const int*   esrc  = (const int*)d_in[1];
    const int*   edst  = (const int*)d_in[2];
    const float* Wp    = (const float*)d_in[3];
    const float* bp    = (const float*)d_in[4];
    const float* Wm    = (const float*)d_in[5];
    const float* bm    = (const float*)d_in[6];
    const float* Wu    = (const float*)d_in[7];
    const float* bu    = (const float*)d_in[8];
    const float* gamma = (const float*)d_in[9];
    const float* beta  = (const float*)d_in[10];
    const float* Wd    = (const float*)d_in[11];
    const float* bd    = (const float*)d_in[12];
    float* out = (float*)d_out;

    int n = in_sizes[0] / 128;
    int e = in_sizes[1];
    int rb = (n + 127) / 128;

    cudaFuncSetAttribute(k_gemm_h, cudaFuncAttributeMaxDynamicSharedMemorySize, GSM_SZ);

    k_zero<<<(n + 255) / 256, 256>>>(n);
    k_prep<<<256, 256>>>(Wp, bp, Wm, bm, Wu);
    // h0 | a | b | c from one GEMM pass
    k_gemm_h<<<dim3(4, rb), 256, GSM_SZ>>>(x, nullptr, nullptr, nullptr, nullptr, n, 0);
    // CSR build + gather (segment mean)
    k_hist<<<(e + 255) / 256, 256>>>(edst, e);
    k_scan<<<1, 1024>>>(n);
    k_scatter<<<(e + 255) / 256, 256>>>(esrc, edst, e);
    k_gather<<<(n * 32 + 255) / 256, 256>>>(n);
    // upd-GEMM fused with relu+LN+graph-pool
    k_gemm_h<<<dim3(1, rb), 256, GSM_SZ>>>(nullptr, Wu + 16384, bu, gamma, beta, n, 1);
    k_final<<<1, 32>>>(Wd, bd, out, n);
}